// round 6
// baseline (speedup 1.0000x reference)
#include <cuda_runtime.h>
#include <cuda_bf16.h>
#include <cstdint>

#define B_ 2
#define H_ 16
#define S_ 2048
#define D_ 128
#define SCALE 0.08838834764831845f   // 1/sqrt(128)
#define NEG (-1e9f)

#define TW 136      // smem tile row stride (bf16 elems)
#define SGW 132     // fp32 staging row stride (floats)

#define TILE_ELEMS (128 * TW)
#define SM_BYTES (4 * TILE_ELEMS * 2)

// Pre-transposed V: Vt[bh][n][k] = V[bh][k][n], split into bf16 hi/lo
__device__ __align__(16) __nv_bfloat16 g_VtHi[(size_t)32 * 128 * 2048];
__device__ __align__(16) __nv_bfloat16 g_VtLo[(size_t)32 * 128 * 2048];
// per (bh, key-tile 0..15, row): (tile row max, tile row sum of exp(s-max))
__device__ __align__(16) float2 g_stats[(size_t)32 * 16 * 2048];

// ---------------------------------------------------------------------------
__device__ __forceinline__ void mma_bf16(float* d,
                                         uint32_t a0, uint32_t a1, uint32_t a2, uint32_t a3,
                                         uint32_t b0, uint32_t b1) {
    asm volatile(
        "mma.sync.aligned.m16n8k16.row.col.f32.bf16.bf16.f32 "
        "{%0,%1,%2,%3}, {%4,%5,%6,%7}, {%8,%9}, {%0,%1,%2,%3};"
        : "+f"(d[0]), "+f"(d[1]), "+f"(d[2]), "+f"(d[3])
        : "r"(a0), "r"(a1), "r"(a2), "r"(a3), "r"(b0), "r"(b1));
}

__device__ __forceinline__ uint32_t pack2(__nv_bfloat16 a, __nv_bfloat16 b) {
    return (uint32_t)__bfloat16_as_ushort(a) | ((uint32_t)__bfloat16_as_ushort(b) << 16);
}

__device__ __forceinline__ void store_hilo4(__nv_bfloat16* hi, __nv_bfloat16* lo,
                                            uint32_t off, float4 v) {
    __nv_bfloat16 h0 = __float2bfloat16(v.x), h1 = __float2bfloat16(v.y);
    __nv_bfloat16 h2 = __float2bfloat16(v.z), h3 = __float2bfloat16(v.w);
    __nv_bfloat16 l0 = __float2bfloat16(v.x - __bfloat162float(h0));
    __nv_bfloat16 l1 = __float2bfloat16(v.y - __bfloat162float(h1));
    __nv_bfloat16 l2 = __float2bfloat16(v.z - __bfloat162float(h2));
    __nv_bfloat16 l3 = __float2bfloat16(v.w - __bfloat162float(h3));
    uint2 hp; hp.x = pack2(h0, h1); hp.y = pack2(h2, h3);
    uint2 lp; lp.x = pack2(l0, l1); lp.y = pack2(l2, l3);
    *(uint2*)(hi + off) = hp;
    *(uint2*)(lo + off) = lp;
}

__device__ __forceinline__ float warpMax(float v) {
    #pragma unroll
    for (int o = 16; o > 0; o >>= 1) v = fmaxf(v, __shfl_xor_sync(0xffffffffu, v, o));
    return v;
}
__device__ __forceinline__ float warpSum(float v) {
    #pragma unroll
    for (int o = 16; o > 0; o >>= 1) v += __shfl_xor_sync(0xffffffffu, v, o);
    return v;
}

// ---------------------------------------------------------------------------
// K0: V -> Vt (transposed) bf16 hi/lo
// ---------------------------------------------------------------------------
__global__ __launch_bounds__(256) void vt_kernel(const float* __restrict__ V) {
    __shared__ float t[32][33];
    const int k0 = blockIdx.x * 32, n0 = blockIdx.y * 32, bh = blockIdx.z;
    const int tid = threadIdx.x, c = tid & 31, r0 = tid >> 5;
    const float* Vb = V + (size_t)bh * S_ * D_;
    #pragma unroll
    for (int rr = r0; rr < 32; rr += 8)
        t[rr][c] = Vb[(size_t)(k0 + rr) * D_ + n0 + c];
    __syncthreads();
    __nv_bfloat16* Hb = g_VtHi + (size_t)bh * D_ * S_;
    __nv_bfloat16* Lb = g_VtLo + (size_t)bh * D_ * S_;
    #pragma unroll
    for (int rr = r0; rr < 32; rr += 8) {
        float x = t[c][rr];
        __nv_bfloat16 h = __float2bfloat16(x);
        __nv_bfloat16 l = __float2bfloat16(x - __bfloat162float(h));
        size_t o = (size_t)(n0 + rr) * S_ + k0 + c;
        Hb[o] = h;
        Lb[o] = l;
    }
}

// ---------------------------------------------------------------------------
// K1: 128x128 score tile -> exp(s - tilemax) in attn scratch + per-row stats.
// 256 threads = 8 warps x 16 rows. Window tiles: stats only, no tile write.
// ---------------------------------------------------------------------------
__global__ __launch_bounds__(256) void scores_stats_kernel(
    const float* __restrict__ Q, const float* __restrict__ K,
    const int* __restrict__ mask, float* __restrict__ attn)
{
    const int bh = blockIdx.z, b = bh >> 4;
    const int i0 = blockIdx.y * 128, j0 = blockIdx.x * 128, tj = blockIdx.x;
    const int tid = threadIdx.x;

    if (j0 + 128 <= (i0 * 4) / 5) {       // fully-window tile: stats only
        if (tid < 128)
            g_stats[((size_t)(bh * 16 + tj)) * S_ + i0 + tid] = make_float2(-1e30f, 0.0f);
        return;
    }

    extern __shared__ __nv_bfloat16 sm[];
    __nv_bfloat16* Qhi = sm;
    __nv_bfloat16* Qlo = sm + TILE_ELEMS;
    __nv_bfloat16* Khi = sm + 2 * TILE_ELEMS;
    __nv_bfloat16* Klo = sm + 3 * TILE_ELEMS;

    const float* Qb = Q + ((size_t)bh * S_ + i0) * D_;
    const float* Kb = K + ((size_t)bh * S_ + j0) * D_;

    #pragma unroll
    for (int it = 0; it < 16; ++it) {
        int idx = it * 256 + tid;
        int row = idx >> 5, c4 = (idx & 31) << 2;
        uint32_t off = row * TW + c4;
        store_hilo4(Qhi, Qlo, off, *(const float4*)&Qb[(size_t)row * D_ + c4]);
        store_hilo4(Khi, Klo, off, *(const float4*)&Kb[(size_t)row * D_ + c4]);
    }
    __syncthreads();

    const int lane = tid & 31, warp = tid >> 5;
    const int g = lane >> 2, c = lane & 3;
    const int m0 = warp * 16;

    float acc[16][4];
    #pragma unroll
    for (int nt = 0; nt < 16; ++nt)
        #pragma unroll
        for (int q = 0; q < 4; ++q) acc[nt][q] = 0.0f;

    const uint32_t aoff0 = (m0 + g) * TW + 2 * c;
    const uint32_t aoff1 = (m0 + g + 8) * TW + 2 * c;

    #pragma unroll
    for (int ks = 0; ks < 8; ++ks) {
        const int k0 = ks * 16;
        uint32_t ah0 = *(const uint32_t*)(Qhi + aoff0 + k0);
        uint32_t ah1 = *(const uint32_t*)(Qhi + aoff1 + k0);
        uint32_t ah2 = *(const uint32_t*)(Qhi + aoff0 + k0 + 8);
        uint32_t ah3 = *(const uint32_t*)(Qhi + aoff1 + k0 + 8);
        uint32_t al0 = *(const uint32_t*)(Qlo + aoff0 + k0);
        uint32_t al1 = *(const uint32_t*)(Qlo + aoff1 + k0);
        uint32_t al2 = *(const uint32_t*)(Qlo + aoff0 + k0 + 8);
        uint32_t al3 = *(const uint32_t*)(Qlo + aoff1 + k0 + 8);
        #pragma unroll
        for (int nt = 0; nt < 16; ++nt) {
            uint32_t boff = (nt * 8 + g) * TW + k0 + 2 * c;
            uint32_t bh0 = *(const uint32_t*)(Khi + boff);
            uint32_t bh1 = *(const uint32_t*)(Khi + boff + 8);
            uint32_t bl0 = *(const uint32_t*)(Klo + boff);
            uint32_t bl1 = *(const uint32_t*)(Klo + boff + 8);
            mma_bf16(acc[nt], ah0, ah1, ah2, ah3, bh0, bh1);
            mma_bf16(acc[nt], ah0, ah1, ah2, ah3, bl0, bl1);
            mma_bf16(acc[nt], al0, al1, al2, al3, bh0, bh1);
        }
    }
    __syncthreads();

    float* stg = (float*)sm;
    #pragma unroll
    for (int nt = 0; nt < 16; ++nt) {
        *(float2*)&stg[(m0 + g) * SGW + nt * 8 + 2 * c]     = make_float2(acc[nt][0], acc[nt][1]);
        *(float2*)&stg[(m0 + g + 8) * SGW + nt * 8 + 2 * c] = make_float2(acc[nt][2], acc[nt][3]);
    }
    __syncthreads();

    // scale + mask + window in staging
    const int* mB = mask + (size_t)b * S_ * S_;
    #pragma unroll
    for (int it = 0; it < 16; ++it) {
        int idx = it * 256 + tid;
        int r = idx >> 5, cc = (idx & 31) * 4;
        int i = i0 + r, thr = (i * 4) / 5, j = j0 + cc;
        int4 mv = *(const int4*)&mB[(size_t)i * S_ + j];
        float4 s = *(float4*)&stg[r * SGW + cc];
        s.x = (mv.x || (j + 0) < thr) ? NEG : s.x * SCALE;
        s.y = (mv.y || (j + 1) < thr) ? NEG : s.y * SCALE;
        s.z = (mv.z || (j + 2) < thr) ? NEG : s.z * SCALE;
        s.w = (mv.w || (j + 3) < thr) ? NEG : s.w * SCALE;
        *(float4*)&stg[r * SGW + cc] = s;
    }
    __syncthreads();

    // per-row tile stats; write exp(s - tilemax) + stats
    float* attnBase = attn + ((size_t)bh * S_ + i0) * S_ + j0;
    #pragma unroll
    for (int it = 0; it < 16; ++it) {
        int r = warp * 16 + it;
        float4 v = *(float4*)&stg[r * SGW + lane * 4];
        float mx = fmaxf(fmaxf(v.x, v.y), fmaxf(v.z, v.w));
        mx = warpMax(mx);
        float4 e;
        e.x = __expf(v.x - mx); e.y = __expf(v.y - mx);
        e.z = __expf(v.z - mx); e.w = __expf(v.w - mx);
        float sum = (e.x + e.y) + (e.z + e.w);
        sum = warpSum(sum);
        *(float4*)&attnBase[(size_t)r * S_ + lane * 4] = e;
        if (lane == 0)
            g_stats[((size_t)(bh * 16 + tj)) * S_ + i0 + r] = make_float2(mx, sum);
    }
}

// ---------------------------------------------------------------------------
// K3: merge stats; normalize attn (write final) fused with context GEMM.
// 128x128 output per CTA, 256 threads = 8 warps x 16 rows.
// ---------------------------------------------------------------------------
__global__ __launch_bounds__(256) void norm_context_kernel(
    float* __restrict__ attn, float* __restrict__ ctx)
{
    const int i0 = blockIdx.x * 128, bh = blockIdx.y;
    const int tid = threadIdx.x;
    const int lane = tid & 31, warp = tid >> 5;
    const int g = lane >> 2, c = lane & 3;
    const int m0 = warp * 16;

    extern __shared__ __nv_bfloat16 sm[];
    __nv_bfloat16* Phi = sm;
    __nv_bfloat16* Plo = sm + TILE_ELEMS;
    __nv_bfloat16* Vhi = sm + 2 * TILE_ELEMS;
    __nv_bfloat16* Vlo = sm + 3 * TILE_ELEMS;
    __shared__ float sF[128][16];   // per-row per-tile normalize factor

    // merge split-softmax stats (one row per thread, tid<128)
    if (tid < 128) {
        const size_t row = (size_t)i0 + tid;
        float2 st[16];
        #pragma unroll
        for (int tj = 0; tj < 16; ++tj)
            st[tj] = g_stats[((size_t)(bh * 16 + tj)) * S_ + row];
        float M = -1e30f;
        #pragma unroll
        for (int tj = 0; tj < 16; ++tj) M = fmaxf(M, st[tj].x);
        float e[16], sum = 0.0f;
        #pragma unroll
        for (int tj = 0; tj < 16; ++tj) { e[tj] = __expf(st[tj].x - M); sum += st[tj].y * e[tj]; }
        float inv = 1.0f / sum;
        #pragma unroll
        for (int tj = 0; tj < 16; ++tj) sF[tid][tj] = e[tj] * inv;
    }
    __syncthreads();

    float acc[16][4];
    #pragma unroll
    for (int nt = 0; nt < 16; ++nt)
        #pragma unroll
        for (int q = 0; q < 4; ++q) acc[nt][q] = 0.0f;

    const uint32_t aoff0 = (m0 + g) * TW + 2 * c;
    const uint32_t aoff1 = (m0 + g + 8) * TW + 2 * c;

    float* attnRow = attn + ((size_t)bh * S_ + i0) * S_;
    const __nv_bfloat16* VtH = g_VtHi + (size_t)bh * D_ * S_;
    const __nv_bfloat16* VtL = g_VtLo + (size_t)bh * D_ * S_;

    for (int kt = 0; kt < 16; ++kt) {
        const int k0g = kt * 128;
        if (k0g + 128 <= (i0 * 4) / 5) {   // window tile: final attn = 0 exactly
            const float4 z = make_float4(0.f, 0.f, 0.f, 0.f);
            #pragma unroll
            for (int it = 0; it < 16; ++it) {
                int idx = it * 256 + tid;
                int r = idx >> 5, cc = (idx & 31) * 4;
                *(float4*)&attnRow[(size_t)r * S_ + k0g + cc] = z;
            }
            continue;
        }
        __syncthreads();   // previous iteration's MMA done with smem tiles
        // normalize P tile (1 FMUL/elem), write final attn, split hi/lo
        #pragma unroll
        for (int it = 0; it < 16; ++it) {
            int idx = it * 256 + tid;
            int r = idx >> 5, cc = (idx & 31) * 4;
            float f = sF[r][kt];
            float4 v = *(float4*)&attnRow[(size_t)r * S_ + k0g + cc];
            v.x *= f; v.y *= f; v.z *= f; v.w *= f;
            *(float4*)&attnRow[(size_t)r * S_ + k0g + cc] = v;
            store_hilo4(Phi, Plo, r * TW + cc, v);
        }
        // Vt tiles (bf16 already)
        #pragma unroll
        for (int it = 0; it < 8; ++it) {
            int idx = it * 256 + tid;
            int n = idx >> 4, k8 = (idx & 15) << 3;
            *(uint4*)(Vhi + n * TW + k8) = *(const uint4*)&VtH[(size_t)n * S_ + k0g + k8];
            *(uint4*)(Vlo + n * TW + k8) = *(const uint4*)&VtL[(size_t)n * S_ + k0g + k8];
        }
        __syncthreads();

        #pragma unroll
        for (int ks = 0; ks < 8; ++ks) {
            const int k0 = ks * 16;
            uint32_t ah0 = *(const uint32_t*)(Phi + aoff0 + k0);
            uint32_t ah1 = *(const uint32_t*)(Phi + aoff1 + k0);
            uint32_t ah2 = *(const uint32_t*)(Phi + aoff0 + k0 + 8);
            uint32_t ah3 = *(const uint32_t*)(Phi + aoff1 + k0 + 8);
            uint32_t al0 = *(const uint32_t*)(Plo + aoff0 + k0);
            uint32_t al1 = *(const uint32_t*)(Plo + aoff1 + k0);
            uint32_t al2 = *(const uint32_t*)(Plo + aoff0 + k0 + 8);
            uint32_t al3 = *(const uint32_t*)(Plo + aoff1 + k0 + 8);
            #pragma unroll
            for (int nt = 0; nt < 16; ++nt) {
                uint32_t boff = (nt * 8 + g) * TW + k0 + 2 * c;
                uint32_t bh0 = *(const uint32_t*)(Vhi + boff);
                uint32_t bh1 = *(const uint32_t*)(Vhi + boff + 8);
                uint32_t bl0 = *(const uint32_t*)(Vlo + boff);
                uint32_t bl1 = *(const uint32_t*)(Vlo + boff + 8);
                mma_bf16(acc[nt], ah0, ah1, ah2, ah3, bh0, bh1);
                mma_bf16(acc[nt], ah0, ah1, ah2, ah3, bl0, bl1);
                mma_bf16(acc[nt], al0, al1, al2, al3, bh0, bh1);
            }
        }
    }
    __syncthreads();

    float* stg = (float*)sm;
    #pragma unroll
    for (int nt = 0; nt < 16; ++nt) {
        *(float2*)&stg[(m0 + g) * SGW + nt * 8 + 2 * c]     = make_float2(acc[nt][0], acc[nt][1]);
        *(float2*)&stg[(m0 + g + 8) * SGW + nt * 8 + 2 * c] = make_float2(acc[nt][2], acc[nt][3]);
    }
    __syncthreads();

    #pragma unroll
    for (int it = 0; it < 16; ++it) {
        int idx = it * 256 + tid;
        int r = idx >> 5, c4 = (idx & 31) << 2;
        *(float4*)&ctx[((size_t)bh * S_ + i0 + r) * D_ + c4] = *(float4*)&stg[r * SGW + c4];
    }
}

// ---------------------------------------------------------------------------
// kernel_launch
// ---------------------------------------------------------------------------
extern "C" void kernel_launch(void* const* d_in, const int* in_sizes, int n_in,
                              void* d_out, int out_size)
{
    const float* Q    = (const float*)d_in[0];
    const float* K    = (const float*)d_in[1];
    const float* V    = (const float*)d_in[2];
    const int*   mask = (const int*)d_in[3];

    float* out  = (float*)d_out;
    float* ctx  = out;
    float* attn = out + (size_t)B_ * H_ * S_ * D_;

    static bool attrs_set = false;
    if (!attrs_set) {
        cudaFuncSetAttribute(scores_stats_kernel, cudaFuncAttributeMaxDynamicSharedMemorySize, SM_BYTES);
        cudaFuncSetAttribute(norm_context_kernel, cudaFuncAttributeMaxDynamicSharedMemorySize, SM_BYTES);
        attrs_set = true;
    }

    vt_kernel<<<dim3(S_ / 32, D_ / 32, B_ * H_), 256>>>(V);

    dim3 gA(S_ / 128, S_ / 128, B_ * H_);     // (16, 16, 32)
    scores_stats_kernel<<<gA, 256, SM_BYTES>>>(Q, K, mask, attn);

    dim3 gB(S_ / 128, B_ * H_);               // (16, 32)
    norm_context_kernel<<<gB, 256, SM_BYTES>>>(attn, ctx);

    (void)in_sizes; (void)n_in; (void)out_size;
}

// round 8
// speedup vs baseline: 1.2915x; 1.2915x over previous
#include <cuda_runtime.h>
#include <cuda_bf16.h>
#include <cstdint>

#define B_ 2
#define H_ 16
#define S_ 2048
#define D_ 128
#define SCALE 0.08838834764831845f   // 1/sqrt(128)
#define NEG (-1e9f)

#define TW 136      // smem tile row stride (bf16 elems)
#define SGW 132     // fp32 staging row stride (floats)

#define TILE_ELEMS (128 * TW)
#define SM_BYTES (4 * TILE_ELEMS * 2)

// Pre-transposed V: Vt[bh][n][k] = V[bh][k][n], split into bf16 hi/lo
__device__ __align__(16) __nv_bfloat16 g_VtHi[(size_t)32 * 128 * 2048];
__device__ __align__(16) __nv_bfloat16 g_VtLo[(size_t)32 * 128 * 2048];

// ---------------------------------------------------------------------------
__device__ __forceinline__ void mma_bf16(float* d,
                                         uint32_t a0, uint32_t a1, uint32_t a2, uint32_t a3,
                                         uint32_t b0, uint32_t b1) {
    asm volatile(
        "mma.sync.aligned.m16n8k16.row.col.f32.bf16.bf16.f32 "
        "{%0,%1,%2,%3}, {%4,%5,%6,%7}, {%8,%9}, {%0,%1,%2,%3};"
        : "+f"(d[0]), "+f"(d[1]), "+f"(d[2]), "+f"(d[3])
        : "r"(a0), "r"(a1), "r"(a2), "r"(a3), "r"(b0), "r"(b1));
}

__device__ __forceinline__ void ldm_x4(uint32_t& r0, uint32_t& r1, uint32_t& r2, uint32_t& r3,
                                       uint32_t addr) {
    asm volatile("ldmatrix.sync.aligned.m8n8.x4.shared.b16 {%0,%1,%2,%3}, [%4];"
                 : "=r"(r0), "=r"(r1), "=r"(r2), "=r"(r3) : "r"(addr));
}

__device__ __forceinline__ uint32_t smem_u32(const void* p) {
    return (uint32_t)__cvta_generic_to_shared(p);
}

__device__ __forceinline__ uint32_t pack2(__nv_bfloat16 a, __nv_bfloat16 b) {
    return (uint32_t)__bfloat16_as_ushort(a) | ((uint32_t)__bfloat16_as_ushort(b) << 16);
}

__device__ __forceinline__ void store_hilo4(__nv_bfloat16* hi, __nv_bfloat16* lo,
                                            uint32_t off, float4 v) {
    __nv_bfloat16 h0 = __float2bfloat16(v.x), h1 = __float2bfloat16(v.y);
    __nv_bfloat16 h2 = __float2bfloat16(v.z), h3 = __float2bfloat16(v.w);
    __nv_bfloat16 l0 = __float2bfloat16(v.x - __bfloat162float(h0));
    __nv_bfloat16 l1 = __float2bfloat16(v.y - __bfloat162float(h1));
    __nv_bfloat16 l2 = __float2bfloat16(v.z - __bfloat162float(h2));
    __nv_bfloat16 l3 = __float2bfloat16(v.w - __bfloat162float(h3));
    uint2 hp; hp.x = pack2(h0, h1); hp.y = pack2(h2, h3);
    uint2 lp; lp.x = pack2(l0, l1); lp.y = pack2(l2, l3);
    *(uint2*)(hi + off) = hp;
    *(uint2*)(lo + off) = lp;
}

__device__ __forceinline__ float warpRedMax(float v) {
    #pragma unroll
    for (int o = 16; o > 0; o >>= 1) v = fmaxf(v, __shfl_xor_sync(0xffffffffu, v, o));
    return v;
}
__device__ __forceinline__ float warpRedSum(float v) {
    #pragma unroll
    for (int o = 16; o > 0; o >>= 1) v += __shfl_xor_sync(0xffffffffu, v, o);
    return v;
}

// ---------------------------------------------------------------------------
// K0: V -> Vt (transposed) bf16 hi/lo
// ---------------------------------------------------------------------------
__global__ __launch_bounds__(256) void vt_kernel(const float* __restrict__ V) {
    __shared__ float t[32][33];
    const int k0 = blockIdx.x * 32, n0 = blockIdx.y * 32, bh = blockIdx.z;
    const int tid = threadIdx.x, c = tid & 31, r0 = tid >> 5;
    const float* Vb = V + (size_t)bh * S_ * D_;
    #pragma unroll
    for (int rr = r0; rr < 32; rr += 8)
        t[rr][c] = Vb[(size_t)(k0 + rr) * D_ + n0 + c];
    __syncthreads();
    __nv_bfloat16* Hb = g_VtHi + (size_t)bh * D_ * S_;
    __nv_bfloat16* Lb = g_VtLo + (size_t)bh * D_ * S_;
    #pragma unroll
    for (int rr = r0; rr < 32; rr += 8) {
        float x = t[c][rr];
        __nv_bfloat16 h = __float2bfloat16(x);
        __nv_bfloat16 l = __float2bfloat16(x - __bfloat162float(h));
        size_t o = (size_t)(n0 + rr) * S_ + k0 + c;
        Hb[o] = h;
        Lb[o] = l;
    }
}

// ---------------------------------------------------------------------------
// K1: scores = Q K^T * scale, mask -> attn scratch. 128x128 tile per CTA.
// Window-skipped tiles write NOTHING (softmax zero-fills them).
// ---------------------------------------------------------------------------
__global__ __launch_bounds__(256) void scores_mma_kernel(
    const float* __restrict__ Q, const float* __restrict__ K,
    const int* __restrict__ mask, float* __restrict__ attn)
{
    const int bh = blockIdx.z, b = bh >> 4;
    const int i0 = blockIdx.y * 128, j0 = blockIdx.x * 128;
    const int tid = threadIdx.x;

    if (j0 + 128 <= (i0 * 4) / 5) return;   // fully-window tile: no work

    float* attnBase = attn + ((size_t)bh * S_ + i0) * S_ + j0;

    extern __shared__ __nv_bfloat16 sm[];
    __nv_bfloat16* Qhi = sm;
    __nv_bfloat16* Qlo = sm + TILE_ELEMS;
    __nv_bfloat16* Khi = sm + 2 * TILE_ELEMS;
    __nv_bfloat16* Klo = sm + 3 * TILE_ELEMS;

    const float* Qb = Q + ((size_t)bh * S_ + i0) * D_;
    const float* Kb = K + ((size_t)bh * S_ + j0) * D_;

    #pragma unroll
    for (int it = 0; it < 16; ++it) {
        int idx = it * 256 + tid;
        int row = idx >> 5, c4 = (idx & 31) << 2;
        uint32_t off = row * TW + c4;
        store_hilo4(Qhi, Qlo, off, *(const float4*)&Qb[(size_t)row * D_ + c4]);
        store_hilo4(Khi, Klo, off, *(const float4*)&Kb[(size_t)row * D_ + c4]);
    }
    __syncthreads();

    const int lane = tid & 31, warp = tid >> 5;
    const int g = lane >> 2, c = lane & 3;
    const int m0 = warp * 16;

    float acc[16][4];
    #pragma unroll
    for (int nt = 0; nt < 16; ++nt)
        #pragma unroll
        for (int q = 0; q < 4; ++q) acc[nt][q] = 0.0f;

    // ldmatrix per-thread addresses (bytes)
    const uint32_t aRowOff = ((m0 + (lane & 15)) * TW + (lane >> 4) * 8) * 2;
    const uint32_t bRowOff = ((((lane >> 4) << 3) + (lane & 7)) * TW + ((lane >> 3) & 1) * 8) * 2;
    const uint32_t aHiA = smem_u32(Qhi) + aRowOff;
    const uint32_t aLoA = smem_u32(Qlo) + aRowOff;
    const uint32_t bHiA = smem_u32(Khi) + bRowOff;
    const uint32_t bLoA = smem_u32(Klo) + bRowOff;

    #pragma unroll
    for (int ks = 0; ks < 8; ++ks) {
        const uint32_t kb = ks * 32;   // 16 bf16 = 32 bytes
        uint32_t ah0, ah1, ah2, ah3, al0, al1, al2, al3;
        ldm_x4(ah0, ah1, ah2, ah3, aHiA + kb);
        ldm_x4(al0, al1, al2, al3, aLoA + kb);
        #pragma unroll
        for (int nt = 0; nt < 16; nt += 2) {
            const uint32_t bo = nt * (8 * TW * 2) + kb;
            uint32_t bh0, bh1, bh2, bh3, bl0, bl1, bl2, bl3;
            ldm_x4(bh0, bh1, bh2, bh3, bHiA + bo);
            ldm_x4(bl0, bl1, bl2, bl3, bLoA + bo);
            mma_bf16(acc[nt],     ah0, ah1, ah2, ah3, bh0, bh1);
            mma_bf16(acc[nt],     ah0, ah1, ah2, ah3, bl0, bl1);
            mma_bf16(acc[nt],     al0, al1, al2, al3, bh0, bh1);
            mma_bf16(acc[nt + 1], ah0, ah1, ah2, ah3, bh2, bh3);
            mma_bf16(acc[nt + 1], ah0, ah1, ah2, ah3, bl2, bl3);
            mma_bf16(acc[nt + 1], al0, al1, al2, al3, bh2, bh3);
        }
    }
    __syncthreads();   // done reading tiles; reuse as fp32 staging

    float* stg = (float*)sm;
    #pragma unroll
    for (int nt = 0; nt < 16; ++nt) {
        *(float2*)&stg[(m0 + g) * SGW + nt * 8 + 2 * c]     = make_float2(acc[nt][0], acc[nt][1]);
        *(float2*)&stg[(m0 + g + 8) * SGW + nt * 8 + 2 * c] = make_float2(acc[nt][2], acc[nt][3]);
    }
    __syncthreads();

    const int* mB = mask + (size_t)b * S_ * S_;
    #pragma unroll
    for (int it = 0; it < 16; ++it) {
        int idx = it * 256 + tid;
        int r = idx >> 5, cc = (idx & 31) * 4;
        int i = i0 + r, thr = (i * 4) / 5, j = j0 + cc;
        int4 mv = *(const int4*)&mB[(size_t)i * S_ + j];
        float4 s = *(float4*)&stg[r * SGW + cc];
        float4 v;
        v.x = (mv.x || (j + 0) < thr) ? NEG : s.x * SCALE;
        v.y = (mv.y || (j + 1) < thr) ? NEG : s.y * SCALE;
        v.z = (mv.z || (j + 2) < thr) ? NEG : s.z * SCALE;
        v.w = (mv.w || (j + 3) < thr) ? NEG : s.w * SCALE;
        *(float4*)&attnBase[(size_t)r * S_ + cc] = v;
    }
}

// ---------------------------------------------------------------------------
// K2: row softmax. Reads only [jStart, S); zero-fills [0, jStart).
// jStart = window-skip boundary at 128-tile granularity (matches K1 skip).
// ---------------------------------------------------------------------------
__global__ __launch_bounds__(256) void softmax_kernel(float* __restrict__ attn)
{
    const int row = blockIdx.x;
    const int i = row & (S_ - 1);
    const int i0 = i & ~127;
    const int jStart = (((i0 * 4) / 5) >> 7) << 7;
    float* p = attn + (size_t)row * S_;
    const int tid = threadIdx.x;

    const int n4 = (S_ - jStart) >> 2;       // 128..512 float4s
    float4* p4 = (float4*)(p + jStart);
    const bool val0 = tid < n4;
    const bool val1 = tid + 256 < n4;

    float4 v0 = make_float4(NEG, NEG, NEG, NEG);
    float4 v1 = make_float4(NEG, NEG, NEG, NEG);
    if (val0) v0 = p4[tid];
    if (val1) v1 = p4[tid + 256];

    __shared__ float red[8];

    float m = fmaxf(fmaxf(fmaxf(v0.x, v0.y), fmaxf(v0.z, v0.w)),
                    fmaxf(fmaxf(v1.x, v1.y), fmaxf(v1.z, v1.w)));
    m = warpRedMax(m);
    if ((tid & 31) == 0) red[tid >> 5] = m;
    __syncthreads();
    float bm = red[0];
    #pragma unroll
    for (int k = 1; k < 8; ++k) bm = fmaxf(bm, red[k]);
    __syncthreads();

    v0.x = __expf(v0.x - bm); v0.y = __expf(v0.y - bm);
    v0.z = __expf(v0.z - bm); v0.w = __expf(v0.w - bm);
    v1.x = __expf(v1.x - bm); v1.y = __expf(v1.y - bm);
    v1.z = __expf(v1.z - bm); v1.w = __expf(v1.w - bm);

    float s = 0.0f;
    if (val0) s += (v0.x + v0.y) + (v0.z + v0.w);
    if (val1) s += (v1.x + v1.y) + (v1.z + v1.w);
    s = warpRedSum(s);
    if ((tid & 31) == 0) red[tid >> 5] = s;
    __syncthreads();
    float bs = 0.0f;
    #pragma unroll
    for (int k = 0; k < 8; ++k) bs += red[k];

    const float inv = 1.0f / bs;
    if (val0) {
        v0.x *= inv; v0.y *= inv; v0.z *= inv; v0.w *= inv;
        p4[tid] = v0;
    }
    if (val1) {
        v1.x *= inv; v1.y *= inv; v1.z *= inv; v1.w *= inv;
        p4[tid + 256] = v1;
    }

    // zero-fill skipped window region (exactly matches reference underflow)
    const float4 z = make_float4(0.f, 0.f, 0.f, 0.f);
    const int nz4 = jStart >> 2;
    for (int idx = tid; idx < nz4; idx += 256)
        ((float4*)p)[idx] = z;
}

// ---------------------------------------------------------------------------
// K3: context = attn @ V. 128x128 output per CTA, loop over key tiles.
// ---------------------------------------------------------------------------
__global__ __launch_bounds__(256) void context_mma_kernel(
    const float* __restrict__ attn, float* __restrict__ ctx)
{
    const int i0 = blockIdx.x * 128, bh = blockIdx.y;
    const int tid = threadIdx.x;

    extern __shared__ __nv_bfloat16 sm[];
    __nv_bfloat16* Phi = sm;
    __nv_bfloat16* Plo = sm + TILE_ELEMS;
    __nv_bfloat16* Vhi = sm + 2 * TILE_ELEMS;
    __nv_bfloat16* Vlo = sm + 3 * TILE_ELEMS;

    const float* Pb = attn + ((size_t)bh * S_ + i0) * S_;
    const __nv_bfloat16* VtH = g_VtHi + (size_t)bh * D_ * S_;
    const __nv_bfloat16* VtL = g_VtLo + (size_t)bh * D_ * S_;

    const int lane = tid & 31, warp = tid >> 5;
    const int g = lane >> 2, c = lane & 3;
    const int m0 = warp * 16;

    float acc[16][4];
    #pragma unroll
    for (int nt = 0; nt < 16; ++nt)
        #pragma unroll
        for (int q = 0; q < 4; ++q) acc[nt][q] = 0.0f;

    const uint32_t aRowOff = ((m0 + (lane & 15)) * TW + (lane >> 4) * 8) * 2;
    const uint32_t bRowOff = ((((lane >> 4) << 3) + (lane & 7)) * TW + ((lane >> 3) & 1) * 8) * 2;
    const uint32_t aHiA = smem_u32(Phi) + aRowOff;
    const uint32_t aLoA = smem_u32(Plo) + aRowOff;
    const uint32_t bHiA = smem_u32(Vhi) + bRowOff;
    const uint32_t bLoA = smem_u32(Vlo) + bRowOff;

    const int ktStart = ((i0 * 4) / 5) >> 7;   // first key tile with nonzero P

    for (int kt = ktStart; kt < S_ / 128; ++kt) {
        const int k0g = kt * 128;
        __syncthreads();
        // P tile: fp32 -> hi/lo
        #pragma unroll
        for (int it = 0; it < 16; ++it) {
            int idx = it * 256 + tid;
            int row = idx >> 5, c4 = (idx & 31) << 2;
            store_hilo4(Phi, Plo, row * TW + c4,
                        *(const float4*)&Pb[(size_t)row * S_ + k0g + c4]);
        }
        // Vt tiles: already bf16
        #pragma unroll
        for (int it = 0; it < 8; ++it) {
            int idx = it * 256 + tid;
            int n = idx >> 4, k8 = (idx & 15) << 3;
            *(uint4*)(Vhi + n * TW + k8) = *(const uint4*)&VtH[(size_t)n * S_ + k0g + k8];
            *(uint4*)(Vlo + n * TW + k8) = *(const uint4*)&VtL[(size_t)n * S_ + k0g + k8];
        }
        __syncthreads();

        #pragma unroll
        for (int ks = 0; ks < 8; ++ks) {
            const uint32_t kb = ks * 32;
            uint32_t ah0, ah1, ah2, ah3, al0, al1, al2, al3;
            ldm_x4(ah0, ah1, ah2, ah3, aHiA + kb);
            ldm_x4(al0, al1, al2, al3, aLoA + kb);
            #pragma unroll
            for (int nt = 0; nt < 16; nt += 2) {
                const uint32_t bo = nt * (8 * TW * 2) + kb;
                uint32_t bh0, bh1, bh2, bh3, bl0, bl1, bl2, bl3;
                ldm_x4(bh0, bh1, bh2, bh3, bHiA + bo);
                ldm_x4(bl0, bl1, bl2, bl3, bLoA + bo);
                mma_bf16(acc[nt],     ah0, ah1, ah2, ah3, bh0, bh1);
                mma_bf16(acc[nt],     ah0, ah1, ah2, ah3, bl0, bl1);
                mma_bf16(acc[nt],     al0, al1, al2, al3, bh0, bh1);
                mma_bf16(acc[nt + 1], ah0, ah1, ah2, ah3, bh2, bh3);
                mma_bf16(acc[nt + 1], ah0, ah1, ah2, ah3, bl2, bl3);
                mma_bf16(acc[nt + 1], al0, al1, al2, al3, bh2, bh3);
            }
        }
    }
    __syncthreads();

    float* stg = (float*)sm;
    #pragma unroll
    for (int nt = 0; nt < 16; ++nt) {
        *(float2*)&stg[(m0 + g) * SGW + nt * 8 + 2 * c]     = make_float2(acc[nt][0], acc[nt][1]);
        *(float2*)&stg[(m0 + g + 8) * SGW + nt * 8 + 2 * c] = make_float2(acc[nt][2], acc[nt][3]);
    }
    __syncthreads();

    #pragma unroll
    for (int it = 0; it < 16; ++it) {
        int idx = it * 256 + tid;
        int r = idx >> 5, c4 = (idx & 31) << 2;
        *(float4*)&ctx[((size_t)bh * S_ + i0 + r) * D_ + c4] = *(float4*)&stg[r * SGW + c4];
    }
}

// ---------------------------------------------------------------------------
// kernel_launch
// ---------------------------------------------------------------------------
extern "C" void kernel_launch(void* const* d_in, const int* in_sizes, int n_in,
                              void* d_out, int out_size)
{
    const float* Q    = (const float*)d_in[0];
    const float* K    = (const float*)d_in[1];
    const float* V    = (const float*)d_in[2];
    const int*   mask = (const int*)d_in[3];

    float* out  = (float*)d_out;
    float* ctx  = out;
    float* attn = out + (size_t)B_ * H_ * S_ * D_;

    static bool attrs_set = false;
    if (!attrs_set) {
        cudaFuncSetAttribute(scores_mma_kernel, cudaFuncAttributeMaxDynamicSharedMemorySize, SM_BYTES);
        cudaFuncSetAttribute(context_mma_kernel, cudaFuncAttributeMaxDynamicSharedMemorySize, SM_BYTES);
        attrs_set = true;
    }

    vt_kernel<<<dim3(S_ / 32, D_ / 32, B_ * H_), 256>>>(V);

    dim3 g1(S_ / 128, S_ / 128, B_ * H_);
    scores_mma_kernel<<<g1, 256, SM_BYTES>>>(Q, K, mask, attn);

    softmax_kernel<<<B_ * H_ * S_, 256>>>(attn);

    dim3 g3(S_ / 128, B_ * H_);
    context_mma_kernel<<<g3, 256, SM_BYTES>>>(attn, ctx);

    (void)in_sizes; (void)n_in; (void)out_size;
}